// round 7
// baseline (speedup 1.0000x reference)
#include <cuda_runtime.h>
#include <cuda_bf16.h>
#include <cuda_fp8.h>
#include <math_constants.h>
#include <cstdint>

// TripletLoss: features [4096,2048] f32, labels [4096] i32 -> scalar f32.
//  K0: split x -> Hs=16*bf16(x) [bf16], H8=e4m3(H), L8=e4m3(256*(x-H)) + norms
//  K1: Gram via mma.sync: HH in bf16 k16, cross terms in fp8 k32 (half the
//      instructions). acc = 256*dot. 128x256 tiles, upper triangle (272 CTAs),
//      fused distance + batch-hard epilogue (row+col anchors).
//  K2: final loss reduction
// Harness compiles plain compute_103 => no tcgen05; mma.sync only.

#define NROWS 4096
#define DDIM  2048
#define MARGIN 0.3f

#define TM 128
#define TN 256
#define BK 64
#define NCHUNK (DDIM / BK)   // 32

__device__ float         g_sq[NROWS];
__device__ unsigned int  g_ap[NROWS];
__device__ unsigned int  g_an[NROWS];
__device__ __nv_bfloat16 g_Hs[(size_t)NROWS * DDIM];  // 16 MB  (16*H, bf16)
__device__ uint8_t       g_H8[(size_t)NROWS * DDIM];  //  8 MB  (e4m3 H)
__device__ uint8_t       g_L8[(size_t)NROWS * DDIM];  //  8 MB  (e4m3 256*L)

// ---------------- SMEM layout (dynamic, 1 CTA/SM) ----------------
// Stage: A_Hs 16K | A8[H8|L8] 16K | B_Hs 32K | B8[H8|L8] 32K  (128B rows)
#define STAGE_BYTES 98304u
#define OFF_AHS 0u
#define OFF_A8  16384u
#define OFF_BHS 32768u
#define OFF_B8  65536u
#define META   196608u
#define OFF_LR      (META + 0u)
#define OFF_LC      (META + 512u)
#define OFF_SQR     (META + 1536u)
#define OFF_SQC     (META + 2048u)
#define OFF_SCAP    (META + 3072u)
#define OFF_SCAN    (META + 4096u)
#define SMEM_TOTAL  (META + 5120u)

// ---------------- PTX helpers ----------------
__device__ __forceinline__ uint32_t smem_u32(const void* p) {
    uint32_t a;
    asm("{ .reg .u64 t; cvta.to.shared.u64 t, %1; cvt.u32.u64 %0, t; }" : "=r"(a) : "l"(p));
    return a;
}
__device__ __forceinline__ void cp16(uint32_t saddr, const void* gaddr) {
    asm volatile("cp.async.cg.shared.global [%0], [%1], 16;" :: "r"(saddr), "l"(gaddr));
}
__device__ __forceinline__ void cp_commit() {
    asm volatile("cp.async.commit_group;" ::: "memory");
}
template <int N> __device__ __forceinline__ void cp_wait() {
    asm volatile("cp.async.wait_group %0;" :: "n"(N) : "memory");
}
__device__ __forceinline__ void ldsm4(uint32_t (&r)[4], uint32_t a) {
    asm volatile("ldmatrix.sync.aligned.m8n8.x4.shared.b16 {%0,%1,%2,%3}, [%4];"
                 : "=r"(r[0]), "=r"(r[1]), "=r"(r[2]), "=r"(r[3]) : "r"(a));
}
__device__ __forceinline__ void mma_bf16(float (&c)[4], const uint32_t (&a)[4],
                                         uint32_t b0, uint32_t b1) {
    asm volatile(
        "mma.sync.aligned.m16n8k16.row.col.f32.bf16.bf16.f32 "
        "{%0,%1,%2,%3}, {%4,%5,%6,%7}, {%8,%9}, {%0,%1,%2,%3};"
        : "+f"(c[0]), "+f"(c[1]), "+f"(c[2]), "+f"(c[3])
        : "r"(a[0]), "r"(a[1]), "r"(a[2]), "r"(a[3]), "r"(b0), "r"(b1));
}
__device__ __forceinline__ void mma_fp8(float (&c)[4], const uint32_t (&a)[4],
                                        uint32_t b0, uint32_t b1) {
    asm volatile(
        "mma.sync.aligned.m16n8k32.row.col.f32.e4m3.e4m3.f32 "
        "{%0,%1,%2,%3}, {%4,%5,%6,%7}, {%8,%9}, {%0,%1,%2,%3};"
        : "+f"(c[0]), "+f"(c[1]), "+f"(c[2]), "+f"(c[3])
        : "r"(a[0]), "r"(a[1]), "r"(a[2]), "r"(a[3]), "r"(b0), "r"(b1));
}
__device__ __forceinline__ uint32_t swz(uint32_t off) {
    return off ^ ((off >> 3) & 0x70);
}

// ---------------------------------------------------------------------------
// K0: split + row squared norms + accumulator init.
// ---------------------------------------------------------------------------
__global__ __launch_bounds__(256) void conv_kernel(const float* __restrict__ x) {
    const int row = blockIdx.x;
    const float4* xr = (const float4*)(x + (size_t)row * DDIM);
    __nv_bfloat162* hp = (__nv_bfloat162*)(g_Hs + (size_t)row * DDIM);
    uint32_t* h8p = (uint32_t*)(g_H8 + (size_t)row * DDIM);
    uint32_t* l8p = (uint32_t*)(g_L8 + (size_t)row * DDIM);
    float s = 0.f;
    #pragma unroll 2
    for (int i = threadIdx.x; i < DDIM / 4; i += 256) {
        float4 v = xr[i];
        s += v.x * v.x + v.y * v.y + v.z * v.z + v.w * v.w;
        float h0 = __bfloat162float(__float2bfloat16_rn(v.x));
        float h1 = __bfloat162float(__float2bfloat16_rn(v.y));
        float h2 = __bfloat162float(__float2bfloat16_rn(v.z));
        float h3 = __bfloat162float(__float2bfloat16_rn(v.w));
        hp[2 * i + 0] = __floats2bfloat162_rn(16.f * h0, 16.f * h1);  // exact scale
        hp[2 * i + 1] = __floats2bfloat162_rn(16.f * h2, 16.f * h3);
        uint32_t hq = (uint32_t)__nv_cvt_float_to_fp8(h0, __NV_SATFINITE, __NV_E4M3)
                    | ((uint32_t)__nv_cvt_float_to_fp8(h1, __NV_SATFINITE, __NV_E4M3) << 8)
                    | ((uint32_t)__nv_cvt_float_to_fp8(h2, __NV_SATFINITE, __NV_E4M3) << 16)
                    | ((uint32_t)__nv_cvt_float_to_fp8(h3, __NV_SATFINITE, __NV_E4M3) << 24);
        uint32_t lq = (uint32_t)__nv_cvt_float_to_fp8(256.f * (v.x - h0), __NV_SATFINITE, __NV_E4M3)
                    | ((uint32_t)__nv_cvt_float_to_fp8(256.f * (v.y - h1), __NV_SATFINITE, __NV_E4M3) << 8)
                    | ((uint32_t)__nv_cvt_float_to_fp8(256.f * (v.z - h2), __NV_SATFINITE, __NV_E4M3) << 16)
                    | ((uint32_t)__nv_cvt_float_to_fp8(256.f * (v.w - h3), __NV_SATFINITE, __NV_E4M3) << 24);
        h8p[i] = hq;
        l8p[i] = lq;
    }
    #pragma unroll
    for (int o = 16; o; o >>= 1) s += __shfl_xor_sync(0xffffffffu, s, o);
    __shared__ float ws[8];
    if ((threadIdx.x & 31) == 0) ws[threadIdx.x >> 5] = s;
    __syncthreads();
    if (threadIdx.x == 0) {
        float t = 0.f;
        #pragma unroll
        for (int w = 0; w < 8; w++) t += ws[w];
        g_sq[row] = t;
        g_ap[row] = 0u;
        g_an[row] = 0x7f800000u;
    }
}

// ---------------------------------------------------------------------------
// K1: Gram (bf16 HH + fp8 cross) + fused batch-hard epilogue.
// 8 warps; CTA 128x256; warp 64x64 (2x4 grid).
// ---------------------------------------------------------------------------
__global__ __launch_bounds__(256, 1) void gram_kernel(const int* __restrict__ lbl) {
    extern __shared__ __align__(1024) char smem[];
    int rt = 0, ct = 0;
    {
        int rem = blockIdx.x;
        #pragma unroll 1
        for (int h = 0; h < 16; ++h) {
            int half = 16 - h;
            if (rem < 2 * half) {
                if (rem < half) { rt = 2 * h;     ct = h + rem; }
                else            { rt = 2 * h + 1; ct = h + rem - half; }
                break;
            }
            rem -= 2 * half;
        }
    }
    const int row0 = rt * TM;
    const int col0 = ct * TN;
    const int tid = threadIdx.x;
    const int wid = tid >> 5;
    const int lid = tid & 31;
    const int wr = wid >> 2;
    const int wc = wid & 3;
    const uint32_t sb = smem_u32(smem);

    int*      lr   = (int*)(smem + OFF_LR);
    int*      lc   = (int*)(smem + OFF_LC);
    float*    sqr  = (float*)(smem + OFF_SQR);
    float*    sqc  = (float*)(smem + OFF_SQC);
    unsigned* scap = (unsigned*)(smem + OFF_SCAP);
    unsigned* scan = (unsigned*)(smem + OFF_SCAN);

    if (tid < 128) { lr[tid] = lbl[row0 + tid]; sqr[tid] = g_sq[row0 + tid]; }
    lc[tid]   = lbl[col0 + tid];
    sqc[tid]  = g_sq[col0 + tid];
    scap[tid] = 0u;
    scan[tid] = 0x7f800000u;

    auto load_chunk = [&](int n, int b) {
        const int k0 = n * BK;
        const uint32_t base = sb + (uint32_t)b * STAGE_BYTES;
        #pragma unroll
        for (int u4 = 0; u4 < 4; ++u4) {               // A tiles: 128 rows x 8 segs
            int u = tid + u4 * 256;
            int r = u >> 3, s = u & 7;
            uint32_t sw = swz((uint32_t)u << 4);
            cp16(base + OFF_AHS + sw,
                 g_Hs + (size_t)(row0 + r) * DDIM + k0 + s * 8);      // 8 bf16 = 16B
            const uint8_t* src8 = (s < 4)
                ? g_H8 + (size_t)(row0 + r) * DDIM + k0 + s * 16
                : g_L8 + (size_t)(row0 + r) * DDIM + k0 + (s - 4) * 16;
            cp16(base + OFF_A8 + sw, src8);
        }
        #pragma unroll
        for (int u4 = 0; u4 < 8; ++u4) {               // B tiles: 256 rows x 8 segs
            int u = tid + u4 * 256;
            int r = u >> 3, s = u & 7;
            uint32_t sw = swz((uint32_t)u << 4);
            cp16(base + OFF_BHS + sw,
                 g_Hs + (size_t)(col0 + r) * DDIM + k0 + s * 8);
            const uint8_t* src8 = (s < 4)
                ? g_H8 + (size_t)(col0 + r) * DDIM + k0 + s * 16
                : g_L8 + (size_t)(col0 + r) * DDIM + k0 + (s - 4) * 16;
            cp16(base + OFF_B8 + sw, src8);
        }
        cp_commit();
    };

    float acc[4][8][4];
    #pragma unroll
    for (int i = 0; i < 4; i++)
        #pragma unroll
        for (int j = 0; j < 8; j++)
            #pragma unroll
            for (int v = 0; v < 4; v++) acc[i][j][v] = 0.f;

    const int fr = lid & 15;
    const uint32_t kb16 = (uint32_t)(lid >> 4) * 16;

    load_chunk(0, 0);

    for (int c = 0; c < NCHUNK; ++c) {
        const int b = c & 1;
        if (c + 1 < NCHUNK) { load_chunk(c + 1, (c + 1) & 1); cp_wait<1>(); }
        else                { cp_wait<0>(); }
        __syncthreads();

        const uint32_t base = sb + (uint32_t)b * STAGE_BYTES;
        const uint32_t arow = (uint32_t)(wr * 64 + fr);   // + i*16 below
        const uint32_t brow = (uint32_t)(wc * 64 + fr);

        // ---- HH term: bf16 k16, 4 k-steps ----
        #pragma unroll
        for (int ks = 0; ks < 4; ++ks) {
            const uint32_t kb = (uint32_t)ks * 32 + kb16;
            uint32_t ah[4][4], bh[4][4];
            #pragma unroll
            for (int i = 0; i < 4; ++i)
                ldsm4(ah[i], base + OFF_AHS + swz((arow + i * 16) * 128 + kb));
            #pragma unroll
            for (int p = 0; p < 4; ++p)
                ldsm4(bh[p], base + OFF_BHS + swz((brow + p * 16) * 128 + kb));
            #pragma unroll
            for (int i = 0; i < 4; ++i)
                #pragma unroll
                for (int j = 0; j < 8; ++j)
                    mma_bf16(acc[i][j], ah[i],
                             (j & 1) ? bh[j >> 1][1] : bh[j >> 1][0],
                             (j & 1) ? bh[j >> 1][3] : bh[j >> 1][2]);
        }

        // ---- cross terms: fp8 k32, 2 k-halves, H8*L8^T + L8*H8^T ----
        #pragma unroll
        for (int kh = 0; kh < 2; ++kh) {
            const uint32_t kb = (uint32_t)kh * 32 + kb16;
            uint32_t aH[4][4], aL[4][4], bH[4][4], bL[4][4];
            #pragma unroll
            for (int i = 0; i < 4; ++i) {
                ldsm4(aH[i], base + OFF_A8 + swz((arow + i * 16) * 128 + kb));
                ldsm4(aL[i], base + OFF_A8 + swz((arow + i * 16) * 128 + 64 + kb));
            }
            #pragma unroll
            for (int p = 0; p < 4; ++p) {
                ldsm4(bH[p], base + OFF_B8 + swz((brow + p * 16) * 128 + kb));
                ldsm4(bL[p], base + OFF_B8 + swz((brow + p * 16) * 128 + 64 + kb));
            }
            #pragma unroll
            for (int i = 0; i < 4; ++i)
                #pragma unroll
                for (int j = 0; j < 8; ++j) {
                    mma_fp8(acc[i][j], aH[i],
                            (j & 1) ? bL[j >> 1][1] : bL[j >> 1][0],
                            (j & 1) ? bL[j >> 1][3] : bL[j >> 1][2]);
                    mma_fp8(acc[i][j], aL[i],
                            (j & 1) ? bH[j >> 1][1] : bH[j >> 1][0],
                            (j & 1) ? bH[j >> 1][3] : bH[j >> 1][2]);
                }
        }
        __syncthreads();
    }

    // ---------------- Epilogue (acc = 256 * dot) ----------------
    const int rq = lid >> 2;
    const int cq = (lid & 3) * 2;
    float rowP[8], rowN[8], colP[16], colN[16];
    #pragma unroll
    for (int t = 0; t < 8; t++)  { rowP[t] = 0.f; rowN[t] = CUDART_INF_F; }
    #pragma unroll
    for (int t = 0; t < 16; t++) { colP[t] = 0.f; colN[t] = CUDART_INF_F; }

    #pragma unroll
    for (int i = 0; i < 4; ++i) {
        const int rlo = wr * 64 + i * 16 + rq;
        const int rhi = rlo + 8;
        const float sq_lo = sqr[rlo], sq_hi = sqr[rhi];
        const int   ll_lo = lr[rlo],  ll_hi = lr[rhi];
        #pragma unroll
        for (int j = 0; j < 8; ++j) {
            const int cbase = wc * 64 + j * 8 + cq;
            #pragma unroll
            for (int v = 0; v < 4; ++v) {
                const int rloc = (v & 2) ? rhi : rlo;
                const int cloc = cbase + (v & 1);
                const float sqi = (v & 2) ? sq_hi : sq_lo;
                const int   li  = (v & 2) ? ll_hi : ll_lo;
                float d2 = fmaf(acc[i][j][v], -2.f / 256.f, sqi + sqc[cloc]);
                float d  = d2 > 0.f ? sqrtf(d2) : 0.f;
                if (row0 + rloc == col0 + cloc) d = 0.f;
                const bool pos = (li == lc[cloc]);
                const float pv = pos ? d : 0.f;
                const float nv = pos ? CUDART_INF_F : d;
                const int ri = i * 2 + ((v & 2) >> 1);
                const int ci = j * 2 + (v & 1);
                rowP[ri] = fmaxf(rowP[ri], pv);
                rowN[ri] = fminf(rowN[ri], nv);
                colP[ci] = fmaxf(colP[ci], pv);
                colN[ci] = fminf(colN[ci], nv);
            }
        }
    }
    #pragma unroll
    for (int t = 0; t < 8; ++t) {
        float p = rowP[t], n = rowN[t];
        #pragma unroll
        for (int o = 1; o <= 2; o <<= 1) {
            p = fmaxf(p, __shfl_xor_sync(0xffffffffu, p, o));
            n = fminf(n, __shfl_xor_sync(0xffffffffu, n, o));
        }
        if ((lid & 3) == 0) {
            const int grow = row0 + wr * 64 + (t >> 1) * 16 + rq + (t & 1) * 8;
            atomicMax(&g_ap[grow], __float_as_uint(p));
            atomicMin(&g_an[grow], __float_as_uint(n));
        }
    }
    #pragma unroll
    for (int t = 0; t < 16; ++t) {
        float p = colP[t], n = colN[t];
        #pragma unroll
        for (int o = 4; o <= 16; o <<= 1) {
            p = fmaxf(p, __shfl_xor_sync(0xffffffffu, p, o));
            n = fminf(n, __shfl_xor_sync(0xffffffffu, n, o));
        }
        if (rq == 0) {
            const int cc = wc * 64 + (t >> 1) * 8 + cq + (t & 1);
            atomicMax(&scap[cc], __float_as_uint(p));
            atomicMin(&scan[cc], __float_as_uint(n));
        }
    }
    __syncthreads();
    atomicMax(&g_ap[col0 + tid], scap[tid]);
    atomicMin(&g_an[col0 + tid], scan[tid]);
}

// ---------------------------------------------------------------------------
// K2: final loss reduction. One block.
// ---------------------------------------------------------------------------
__global__ __launch_bounds__(256) void loss_kernel(float* __restrict__ out) {
    const int tid = threadIdx.x;
    float s = 0.f;
    int c = 0;
    for (int i = tid; i < NROWS; i += 256) {
        float ap = __uint_as_float(g_ap[i]);
        float an = __uint_as_float(g_an[i]);
        if (ap > 0.f && isfinite(an)) {
            s += fmaxf(ap - an + MARGIN, 0.f);
            c += 1;
        }
    }
    #pragma unroll
    for (int o = 16; o; o >>= 1) {
        s += __shfl_xor_sync(0xffffffffu, s, o);
        c += __shfl_xor_sync(0xffffffffu, c, o);
    }
    __shared__ float ws[8];
    __shared__ int wc[8];
    if ((tid & 31) == 0) { ws[tid >> 5] = s; wc[tid >> 5] = c; }
    __syncthreads();
    if (tid == 0) {
        float ts = 0.f; int tc = 0;
        #pragma unroll
        for (int w = 0; w < 8; w++) { ts += ws[w]; tc += wc[w]; }
        out[0] = tc > 0 ? ts / (float)tc : 0.f;
    }
}

// ---------------------------------------------------------------------------
extern "C" void kernel_launch(void* const* d_in, const int* in_sizes, int n_in,
                              void* d_out, int out_size) {
    const float* features = (const float*)d_in[0];
    const int*   labels   = (const int*)d_in[1];
    float*       out      = (float*)d_out;
    (void)in_sizes; (void)n_in; (void)out_size;

    cudaFuncSetAttribute(gram_kernel, cudaFuncAttributeMaxDynamicSharedMemorySize,
                         SMEM_TOTAL);

    conv_kernel<<<NROWS, 256>>>(features);
    gram_kernel<<<272, 256, SMEM_TOTAL>>>(labels);
    loss_kernel<<<1, 256>>>(out);
}

// round 8
// speedup vs baseline: 2.7024x; 2.7024x over previous
#include <cuda_runtime.h>
#include <cuda_fp16.h>
#include <math_constants.h>
#include <cstdint>

// TripletLoss: features [4096,2048] f32, labels [4096] i32 -> scalar f32.
//  K0: convert x -> fp16 + row norms (fp32) + init accumulators
//  K1: single fp16 mma.sync Gram (fp32 accum), 128x256 tiles, BK=128,
//      upper triangle only (272 CTAs), fused distance + batch-hard epilogue
//  K2: final loss reduction
// fp16 single-term: dot err rms ~0.018 -> d err ~2e-4 abs; loss ~3.95,
// tolerance 4e-3 abs -> ~10x margin. (bf16 needed 3-term; fp8 mma is slow
// on the legacy SASS path -- measured R6.)

#define NROWS 4096
#define DDIM  2048
#define MARGIN 0.3f

#define TM 128
#define TN 256
#define BK 128
#define NCHUNK (DDIM / BK)   // 16

__device__ float        g_sq[NROWS];
__device__ unsigned int g_ap[NROWS];
__device__ unsigned int g_an[NROWS];
__device__ __half       g_F[(size_t)NROWS * DDIM];    // 16 MB

// ---------------- SMEM layout (dynamic, 1 CTA/SM) ----------------
// Stage: A 128x128 fp16 (32K, 256B rows) | B 256x128 fp16 (64K)
#define STAGE_BYTES 98304u
#define OFF_A 0u
#define OFF_B 32768u
#define META   196608u
#define OFF_LR      (META + 0u)      // int[128]
#define OFF_LC      (META + 512u)    // int[256]
#define OFF_SQR     (META + 1536u)   // float[128]
#define OFF_SQC     (META + 2048u)   // float[256]
#define OFF_SCAP    (META + 3072u)   // uint[256]
#define OFF_SCAN    (META + 4096u)   // uint[256]
#define SMEM_TOTAL  (META + 5120u)

// ---------------- PTX helpers ----------------
__device__ __forceinline__ uint32_t smem_u32(const void* p) {
    uint32_t a;
    asm("{ .reg .u64 t; cvta.to.shared.u64 t, %1; cvt.u32.u64 %0, t; }" : "=r"(a) : "l"(p));
    return a;
}
__device__ __forceinline__ void cp16(uint32_t saddr, const void* gaddr) {
    asm volatile("cp.async.cg.shared.global [%0], [%1], 16;" :: "r"(saddr), "l"(gaddr));
}
__device__ __forceinline__ void cp_commit() {
    asm volatile("cp.async.commit_group;" ::: "memory");
}
template <int N> __device__ __forceinline__ void cp_wait() {
    asm volatile("cp.async.wait_group %0;" :: "n"(N) : "memory");
}
__device__ __forceinline__ void ldsm4(uint32_t (&r)[4], uint32_t a) {
    asm volatile("ldmatrix.sync.aligned.m8n8.x4.shared.b16 {%0,%1,%2,%3}, [%4];"
                 : "=r"(r[0]), "=r"(r[1]), "=r"(r[2]), "=r"(r[3]) : "r"(a));
}
__device__ __forceinline__ void mma_f16(float (&c)[4], const uint32_t (&a)[4],
                                        uint32_t b0, uint32_t b1) {
    asm volatile(
        "mma.sync.aligned.m16n8k16.row.col.f32.f16.f16.f32 "
        "{%0,%1,%2,%3}, {%4,%5,%6,%7}, {%8,%9}, {%0,%1,%2,%3};"
        : "+f"(c[0]), "+f"(c[1]), "+f"(c[2]), "+f"(c[3])
        : "r"(a[0]), "r"(a[1]), "r"(a[2]), "r"(a[3]), "r"(b0), "r"(b1));
}
// 256B-row swizzle: XOR row bits [8:11) into 16B-group bits [4:7)
__device__ __forceinline__ uint32_t swz(uint32_t off) {
    return off ^ ((off >> 4) & 0x70);
}

// ---------------------------------------------------------------------------
// K0: fp16 convert + row squared norms + accumulator init.
// ---------------------------------------------------------------------------
__global__ __launch_bounds__(256) void conv_kernel(const float* __restrict__ x) {
    const int row = blockIdx.x;
    const float4* xr = (const float4*)(x + (size_t)row * DDIM);
    __half2* fp = (__half2*)(g_F + (size_t)row * DDIM);
    float s = 0.f;
    #pragma unroll 2
    for (int i = threadIdx.x; i < DDIM / 4; i += 256) {
        float4 v = xr[i];
        s += v.x * v.x + v.y * v.y + v.z * v.z + v.w * v.w;
        fp[2 * i + 0] = __floats2half2_rn(v.x, v.y);
        fp[2 * i + 1] = __floats2half2_rn(v.z, v.w);
    }
    #pragma unroll
    for (int o = 16; o; o >>= 1) s += __shfl_xor_sync(0xffffffffu, s, o);
    __shared__ float ws[8];
    if ((threadIdx.x & 31) == 0) ws[threadIdx.x >> 5] = s;
    __syncthreads();
    if (threadIdx.x == 0) {
        float t = 0.f;
        #pragma unroll
        for (int w = 0; w < 8; w++) t += ws[w];
        g_sq[row] = t;
        g_ap[row] = 0u;
        g_an[row] = 0x7f800000u;
    }
}

// ---------------------------------------------------------------------------
// K1: fp16 Gram + fused batch-hard epilogue. 8 warps, CTA 128x256, warp 64x64.
// ---------------------------------------------------------------------------
__global__ __launch_bounds__(256, 1) void gram_kernel(const int* __restrict__ lbl) {
    extern __shared__ __align__(1024) char smem[];
    int rt = 0, ct = 0;
    {
        int rem = blockIdx.x;
        #pragma unroll 1
        for (int h = 0; h < 16; ++h) {
            int half = 16 - h;
            if (rem < 2 * half) {
                if (rem < half) { rt = 2 * h;     ct = h + rem; }
                else            { rt = 2 * h + 1; ct = h + rem - half; }
                break;
            }
            rem -= 2 * half;
        }
    }
    const int row0 = rt * TM;
    const int col0 = ct * TN;
    const int tid = threadIdx.x;
    const int wid = tid >> 5;
    const int lid = tid & 31;
    const int wr = wid >> 2;       // warp row 0..1
    const int wc = wid & 3;        // warp col 0..3
    const uint32_t sb = smem_u32(smem);

    int*      lr   = (int*)(smem + OFF_LR);
    int*      lc   = (int*)(smem + OFF_LC);
    float*    sqr  = (float*)(smem + OFF_SQR);
    float*    sqc  = (float*)(smem + OFF_SQC);
    unsigned* scap = (unsigned*)(smem + OFF_SCAP);
    unsigned* scan = (unsigned*)(smem + OFF_SCAN);

    if (tid < 128) { lr[tid] = lbl[row0 + tid]; sqr[tid] = g_sq[row0 + tid]; }
    lc[tid]   = lbl[col0 + tid];
    sqc[tid]  = g_sq[col0 + tid];
    scap[tid] = 0u;
    scan[tid] = 0x7f800000u;

    auto load_chunk = [&](int n, int b) {
        const int k0 = n * BK;
        const uint32_t base = sb + (uint32_t)b * STAGE_BYTES;
        #pragma unroll
        for (int u8 = 0; u8 < 8; ++u8) {               // A: 128 rows x 16 segs
            int u = tid + u8 * 256;
            int r = u >> 4, s = u & 15;
            uint32_t sw = swz(((uint32_t)r << 8) + ((uint32_t)s << 4));
            cp16(base + OFF_A + sw, g_F + (size_t)(row0 + r) * DDIM + k0 + s * 8);
        }
        #pragma unroll
        for (int u8 = 0; u8 < 16; ++u8) {              // B: 256 rows x 16 segs
            int u = tid + u8 * 256;
            int r = u >> 4, s = u & 15;
            uint32_t sw = swz(((uint32_t)r << 8) + ((uint32_t)s << 4));
            cp16(base + OFF_B + sw, g_F + (size_t)(col0 + r) * DDIM + k0 + s * 8);
        }
        cp_commit();
    };

    float acc[4][8][4];
    #pragma unroll
    for (int i = 0; i < 4; i++)
        #pragma unroll
        for (int j = 0; j < 8; j++)
            #pragma unroll
            for (int v = 0; v < 4; v++) acc[i][j][v] = 0.f;

    const int fr = lid & 15;
    const uint32_t kb16 = (uint32_t)(lid >> 4) * 16;

    load_chunk(0, 0);

    for (int c = 0; c < NCHUNK; ++c) {
        const int b = c & 1;
        if (c + 1 < NCHUNK) { load_chunk(c + 1, (c + 1) & 1); cp_wait<1>(); }
        else                { cp_wait<0>(); }
        __syncthreads();

        const uint32_t base = sb + (uint32_t)b * STAGE_BYTES;
        const uint32_t arow = (uint32_t)(wr * 64 + fr);
        const uint32_t brow = (uint32_t)(wc * 64 + fr);

        #pragma unroll
        for (int ks = 0; ks < 8; ++ks) {               // K=16 per step
            const uint32_t kb = (uint32_t)ks * 32 + kb16;
            uint32_t ah[4][4], bh[4][4];
            #pragma unroll
            for (int i = 0; i < 4; ++i)
                ldsm4(ah[i], base + OFF_A + swz(((arow + i * 16) << 8) + kb));
            #pragma unroll
            for (int p = 0; p < 4; ++p)
                ldsm4(bh[p], base + OFF_B + swz(((brow + p * 16) << 8) + kb));
            #pragma unroll
            for (int i = 0; i < 4; ++i)
                #pragma unroll
                for (int j = 0; j < 8; ++j)
                    mma_f16(acc[i][j], ah[i],
                            (j & 1) ? bh[j >> 1][1] : bh[j >> 1][0],
                            (j & 1) ? bh[j >> 1][3] : bh[j >> 1][2]);
        }
        __syncthreads();
    }

    // ---------------- Epilogue ----------------
    const int rq = lid >> 2;
    const int cq = (lid & 3) * 2;
    float rowP[8], rowN[8], colP[16], colN[16];
    #pragma unroll
    for (int t = 0; t < 8; t++)  { rowP[t] = 0.f; rowN[t] = CUDART_INF_F; }
    #pragma unroll
    for (int t = 0; t < 16; t++) { colP[t] = 0.f; colN[t] = CUDART_INF_F; }

    #pragma unroll
    for (int i = 0; i < 4; ++i) {
        const int rlo = wr * 64 + i * 16 + rq;
        const int rhi = rlo + 8;
        const float sq_lo = sqr[rlo], sq_hi = sqr[rhi];
        const int   ll_lo = lr[rlo],  ll_hi = lr[rhi];
        #pragma unroll
        for (int j = 0; j < 8; ++j) {
            const int cbase = wc * 64 + j * 8 + cq;
            #pragma unroll
            for (int v = 0; v < 4; ++v) {
                const int rloc = (v & 2) ? rhi : rlo;
                const int cloc = cbase + (v & 1);
                const float sqi = (v & 2) ? sq_hi : sq_lo;
                const int   li  = (v & 2) ? ll_hi : ll_lo;
                float d2 = fmaf(acc[i][j][v], -2.f, sqi + sqc[cloc]);
                float d  = d2 > 0.f ? sqrtf(d2) : 0.f;
                if (row0 + rloc == col0 + cloc) d = 0.f;   // exact diagonal
                const bool pos = (li == lc[cloc]);
                const float pv = pos ? d : 0.f;
                const float nv = pos ? CUDART_INF_F : d;
                const int ri = i * 2 + ((v & 2) >> 1);
                const int ci = j * 2 + (v & 1);
                rowP[ri] = fmaxf(rowP[ri], pv);
                rowN[ri] = fminf(rowN[ri], nv);
                colP[ci] = fmaxf(colP[ci], pv);
                colN[ci] = fminf(colN[ci], nv);
            }
        }
    }
    #pragma unroll
    for (int t = 0; t < 8; ++t) {
        float p = rowP[t], n = rowN[t];
        #pragma unroll
        for (int o = 1; o <= 2; o <<= 1) {
            p = fmaxf(p, __shfl_xor_sync(0xffffffffu, p, o));
            n = fminf(n, __shfl_xor_sync(0xffffffffu, n, o));
        }
        if ((lid & 3) == 0) {
            const int grow = row0 + wr * 64 + (t >> 1) * 16 + rq + (t & 1) * 8;
            atomicMax(&g_ap[grow], __float_as_uint(p));
            atomicMin(&g_an[grow], __float_as_uint(n));
        }
    }
    #pragma unroll
    for (int t = 0; t < 16; ++t) {
        float p = colP[t], n = colN[t];
        #pragma unroll
        for (int o = 4; o <= 16; o <<= 1) {
            p = fmaxf(p, __shfl_xor_sync(0xffffffffu, p, o));
            n = fminf(n, __shfl_xor_sync(0xffffffffu, n, o));
        }
        if (rq == 0) {
            const int cc = wc * 64 + (t >> 1) * 8 + cq + (t & 1);
            atomicMax(&scap[cc], __float_as_uint(p));
            atomicMin(&scan[cc], __float_as_uint(n));
        }
    }
    __syncthreads();
    atomicMax(&g_ap[col0 + tid], scap[tid]);
    atomicMin(&g_an[col0 + tid], scan[tid]);
}

// ---------------------------------------------------------------------------
// K2: final loss reduction. One block.
// ---------------------------------------------------------------------------
__global__ __launch_bounds__(256) void loss_kernel(float* __restrict__ out) {
    const int tid = threadIdx.x;
    float s = 0.f;
    int c = 0;
    for (int i = tid; i < NROWS; i += 256) {
        float ap = __uint_as_float(g_ap[i]);
        float an = __uint_as_float(g_an[i]);
        if (ap > 0.f && isfinite(an)) {
            s += fmaxf(ap - an + MARGIN, 0.f);
            c += 1;
        }
    }
    #pragma unroll
    for (int o = 16; o; o >>= 1) {
        s += __shfl_xor_sync(0xffffffffu, s, o);
        c += __shfl_xor_sync(0xffffffffu, c, o);
    }
    __shared__ float ws[8];
    __shared__ int wc[8];
    if ((tid & 31) == 0) { ws[tid >> 5] = s; wc[tid >> 5] = c; }
    __syncthreads();
    if (tid == 0) {
        float ts = 0.f; int tc = 0;
        #pragma unroll
        for (int w = 0; w < 8; w++) { ts += ws[w]; tc += wc[w]; }
        out[0] = tc > 0 ? ts / (float)tc : 0.f;
    }
}

// ---------------------------------------------------------------------------
extern "C" void kernel_launch(void* const* d_in, const int* in_sizes, int n_in,
                              void* d_out, int out_size) {
    const float* features = (const float*)d_in[0];
    const int*   labels   = (const int*)d_in[1];
    float*       out      = (float*)d_out;
    (void)in_sizes; (void)n_in; (void)out_size;

    cudaFuncSetAttribute(gram_kernel, cudaFuncAttributeMaxDynamicSharedMemorySize,
                         SMEM_TOTAL);

    conv_kernel<<<NROWS, 256>>>(features);
    gram_kernel<<<272, 256, SMEM_TOTAL>>>(labels);
    loss_kernel<<<1, 256>>>(out);
}

// round 10
// speedup vs baseline: 2.9170x; 1.0794x over previous
#include <cuda_runtime.h>
#include <cuda_fp16.h>
#include <math_constants.h>
#include <cstdint>

// TripletLoss: features [4096,2048] f32, labels [4096] i32 -> scalar f32.
//  K0: convert x -> fp16 + row norms (fp32) + init accumulators/counter
//  K1: fp16 mma.sync Gram (fp32 accum), 128x256 tiles, BK=64, 4-stage
//      cp.async pipeline (1 barrier/chunk), upper triangle (272 CTAs),
//      fused distance + batch-hard epilogue + last-CTA loss reduction.

#define NROWS 4096
#define DDIM  2048
#define MARGIN 0.3f

#define TM 128
#define TN 256
#define BK 64
#define NCHUNK (DDIM / BK)   // 32
#define NTILES 272

__device__ float        g_sq[NROWS];
__device__ unsigned int g_ap[NROWS];
__device__ unsigned int g_an[NROWS];
__device__ unsigned int g_cnt;
__device__ __half       g_F[(size_t)NROWS * DDIM];    // 16 MB

// ---------------- SMEM layout (dynamic, 1 CTA/SM) ----------------
// Stage (48KB): A 128x64 fp16 (16K, 128B rows) | B 256x64 fp16 (32K)
#define STAGE_BYTES 49152u
#define OFF_A 0u
#define OFF_B 16384u
#define META   196608u               // 4 stages
#define OFF_LR      (META + 0u)      // int[128]
#define OFF_LC      (META + 512u)    // int[256]
#define OFF_SQR     (META + 1536u)   // float[128]
#define OFF_SQC     (META + 2048u)   // float[256]
#define OFF_SCAP    (META + 3072u)   // uint[256]
#define OFF_SCAN    (META + 4096u)   // uint[256]
#define OFF_LAST    (META + 5120u)   // int flag
#define SMEM_TOTAL  (META + 5248u)

// ---------------- PTX helpers ----------------
__device__ __forceinline__ uint32_t smem_u32(const void* p) {
    uint32_t a;
    asm("{ .reg .u64 t; cvta.to.shared.u64 t, %1; cvt.u32.u64 %0, t; }" : "=r"(a) : "l"(p));
    return a;
}
__device__ __forceinline__ void cp16(uint32_t saddr, const void* gaddr) {
    asm volatile("cp.async.cg.shared.global [%0], [%1], 16;" :: "r"(saddr), "l"(gaddr));
}
__device__ __forceinline__ void cp_commit() {
    asm volatile("cp.async.commit_group;" ::: "memory");
}
template <int N> __device__ __forceinline__ void cp_wait() {
    asm volatile("cp.async.wait_group %0;" :: "n"(N) : "memory");
}
__device__ __forceinline__ void ldsm4(uint32_t (&r)[4], uint32_t a) {
    asm volatile("ldmatrix.sync.aligned.m8n8.x4.shared.b16 {%0,%1,%2,%3}, [%4];"
                 : "=r"(r[0]), "=r"(r[1]), "=r"(r[2]), "=r"(r[3]) : "r"(a));
}
__device__ __forceinline__ void mma_f16(float (&c)[4], const uint32_t (&a)[4],
                                        uint32_t b0, uint32_t b1) {
    asm volatile(
        "mma.sync.aligned.m16n8k16.row.col.f32.f16.f16.f32 "
        "{%0,%1,%2,%3}, {%4,%5,%6,%7}, {%8,%9}, {%0,%1,%2,%3};"
        : "+f"(c[0]), "+f"(c[1]), "+f"(c[2]), "+f"(c[3])
        : "r"(a[0]), "r"(a[1]), "r"(a[2]), "r"(a[3]), "r"(b0), "r"(b1));
}
// 128B-row swizzle
__device__ __forceinline__ uint32_t swz(uint32_t off) {
    return off ^ ((off >> 3) & 0x70);
}

// ---------------------------------------------------------------------------
// K0: fp16 convert + row squared norms + init.
// ---------------------------------------------------------------------------
__global__ __launch_bounds__(256) void conv_kernel(const float* __restrict__ x) {
    const int row = blockIdx.x;
    const float4* xr = (const float4*)(x + (size_t)row * DDIM);
    __half2* fp = (__half2*)(g_F + (size_t)row * DDIM);
    float s = 0.f;
    #pragma unroll 2
    for (int i = threadIdx.x; i < DDIM / 4; i += 256) {
        float4 v = xr[i];
        s += v.x * v.x + v.y * v.y + v.z * v.z + v.w * v.w;
        fp[2 * i + 0] = __floats2half2_rn(v.x, v.y);
        fp[2 * i + 1] = __floats2half2_rn(v.z, v.w);
    }
    #pragma unroll
    for (int o = 16; o; o >>= 1) s += __shfl_xor_sync(0xffffffffu, s, o);
    __shared__ float ws[8];
    if ((threadIdx.x & 31) == 0) ws[threadIdx.x >> 5] = s;
    __syncthreads();
    if (threadIdx.x == 0) {
        float t = 0.f;
        #pragma unroll
        for (int w = 0; w < 8; w++) t += ws[w];
        g_sq[row] = t;
        g_ap[row] = 0u;
        g_an[row] = 0x7f800000u;
        if (row == 0) g_cnt = 0u;
    }
}

// ---------------------------------------------------------------------------
// K1: fp16 Gram + fused batch-hard epilogue + last-CTA loss.
// 8 warps, CTA 128x256, warp 64x64 (2x4 grid). 4-stage pipeline.
// ---------------------------------------------------------------------------
__global__ __launch_bounds__(256, 1) void gram_kernel(const int* __restrict__ lbl,
                                                      float* __restrict__ out) {
    extern __shared__ __align__(1024) char smem[];
    int rt = 0, ct = 0;
    {
        int rem = blockIdx.x;
        #pragma unroll 1
        for (int h = 0; h < 16; ++h) {
            int half = 16 - h;
            if (rem < 2 * half) {
                if (rem < half) { rt = 2 * h;     ct = h + rem; }
                else            { rt = 2 * h + 1; ct = h + rem - half; }
                break;
            }
            rem -= 2 * half;
        }
    }
    const int row0 = rt * TM;
    const int col0 = ct * TN;
    const int tid = threadIdx.x;
    const int wid = tid >> 5;
    const int lid = tid & 31;
    const int wr = wid >> 2;
    const int wc = wid & 3;
    const uint32_t sb = smem_u32(smem);

    int*      lr   = (int*)(smem + OFF_LR);
    int*      lc   = (int*)(smem + OFF_LC);
    float*    sqr  = (float*)(smem + OFF_SQR);
    float*    sqc  = (float*)(smem + OFF_SQC);
    unsigned* scap = (unsigned*)(smem + OFF_SCAP);
    unsigned* scan = (unsigned*)(smem + OFF_SCAN);
    int*      lastf = (int*)(smem + OFF_LAST);

    if (tid < 128) { lr[tid] = lbl[row0 + tid]; sqr[tid] = g_sq[row0 + tid]; }
    lc[tid]   = lbl[col0 + tid];
    sqc[tid]  = g_sq[col0 + tid];
    scap[tid] = 0u;
    scan[tid] = 0x7f800000u;

    auto load_chunk = [&](int n) {
        const int k0 = n * BK;
        const uint32_t base = sb + (uint32_t)(n & 3) * STAGE_BYTES;
        #pragma unroll
        for (int u4 = 0; u4 < 4; ++u4) {               // A: 128 rows x 8 segs
            int u = tid + u4 * 256;
            int r = u >> 3, s = u & 7;
            cp16(base + OFF_A + swz((uint32_t)u << 4),
                 g_F + (size_t)(row0 + r) * DDIM + k0 + s * 8);
        }
        #pragma unroll
        for (int u4 = 0; u4 < 8; ++u4) {               // B: 256 rows x 8 segs
            int u = tid + u4 * 256;
            int r = u >> 3, s = u & 7;
            cp16(base + OFF_B + swz((uint32_t)u << 4),
                 g_F + (size_t)(col0 + r) * DDIM + k0 + s * 8);
        }
        cp_commit();
    };

    float acc[4][8][4];
    #pragma unroll
    for (int i = 0; i < 4; i++)
        #pragma unroll
        for (int j = 0; j < 8; j++)
            #pragma unroll
            for (int v = 0; v < 4; v++) acc[i][j][v] = 0.f;

    const int fr = lid & 15;
    const uint32_t kb16 = (uint32_t)(lid >> 4) * 16;

    load_chunk(0);
    load_chunk(1);
    load_chunk(2);

    #pragma unroll 1
    for (int c = 0; c < NCHUNK; ++c) {
        // chunk c complete; single barrier also protects buffer (c+3)&3 reuse
        if      (c <= NCHUNK - 3) cp_wait<2>();
        else if (c == NCHUNK - 2) cp_wait<1>();
        else                      cp_wait<0>();
        __syncthreads();
        if (c + 3 < NCHUNK) load_chunk(c + 3);

        const uint32_t base = sb + (uint32_t)(c & 3) * STAGE_BYTES;
        const uint32_t arow = (uint32_t)(wr * 64 + fr);
        const uint32_t brow = (uint32_t)(wc * 64 + fr);

        #pragma unroll
        for (int ks = 0; ks < 4; ++ks) {               // K=16 per step
            const uint32_t kb = (uint32_t)ks * 32 + kb16;
            uint32_t ah[4][4], bh[4][4];
            #pragma unroll
            for (int i = 0; i < 4; ++i)
                ldsm4(ah[i], base + OFF_A + swz(((arow + i * 16) << 7) + kb));
            #pragma unroll
            for (int p = 0; p < 4; ++p)
                ldsm4(bh[p], base + OFF_B + swz(((brow + p * 16) << 7) + kb));
            #pragma unroll
            for (int i = 0; i < 4; ++i)
                #pragma unroll
                for (int j = 0; j < 8; ++j)
                    mma_f16(acc[i][j], ah[i],
                            (j & 1) ? bh[j >> 1][1] : bh[j >> 1][0],
                            (j & 1) ? bh[j >> 1][3] : bh[j >> 1][2]);
        }
    }

    // ---------------- Epilogue ----------------
    const int rq = lid >> 2;
    const int cq = (lid & 3) * 2;
    float rowP[8], rowN[8], colP[16], colN[16];
    #pragma unroll
    for (int t = 0; t < 8; t++)  { rowP[t] = 0.f; rowN[t] = CUDART_INF_F; }
    #pragma unroll
    for (int t = 0; t < 16; t++) { colP[t] = 0.f; colN[t] = CUDART_INF_F; }

    #pragma unroll
    for (int i = 0; i < 4; ++i) {
        const int rlo = wr * 64 + i * 16 + rq;
        const int rhi = rlo + 8;
        const float sq_lo = sqr[rlo], sq_hi = sqr[rhi];
        const int   ll_lo = lr[rlo],  ll_hi = lr[rhi];
        #pragma unroll
        for (int j = 0; j < 8; ++j) {
            const int cbase = wc * 64 + j * 8 + cq;
            #pragma unroll
            for (int v = 0; v < 4; ++v) {
                const int rloc = (v & 2) ? rhi : rlo;
                const int cloc = cbase + (v & 1);
                const float sqi = (v & 2) ? sq_hi : sq_lo;
                const int   li  = (v & 2) ? ll_hi : ll_lo;
                float d2 = fmaf(acc[i][j][v], -2.f, sqi + sqc[cloc]);
                float d  = d2 > 0.f ? sqrtf(d2) : 0.f;
                if (row0 + rloc == col0 + cloc) d = 0.f;   // exact diagonal
                const bool pos = (li == lc[cloc]);
                const float pv = pos ? d : 0.f;
                const float nv = pos ? CUDART_INF_F : d;
                const int ri = i * 2 + ((v & 2) >> 1);
                const int ci = j * 2 + (v & 1);
                rowP[ri] = fmaxf(rowP[ri], pv);
                rowN[ri] = fminf(rowN[ri], nv);
                colP[ci] = fmaxf(colP[ci], pv);
                colN[ci] = fminf(colN[ci], nv);
            }
        }
    }
    #pragma unroll
    for (int t = 0; t < 8; ++t) {
        float p = rowP[t], n = rowN[t];
        #pragma unroll
        for (int o = 1; o <= 2; o <<= 1) {
            p = fmaxf(p, __shfl_xor_sync(0xffffffffu, p, o));
            n = fminf(n, __shfl_xor_sync(0xffffffffu, n, o));
        }
        if ((lid & 3) == 0) {
            const int grow = row0 + wr * 64 + (t >> 1) * 16 + rq + (t & 1) * 8;
            atomicMax(&g_ap[grow], __float_as_uint(p));
            atomicMin(&g_an[grow], __float_as_uint(n));
        }
    }
    #pragma unroll
    for (int t = 0; t < 16; ++t) {
        float p = colP[t], n = colN[t];
        #pragma unroll
        for (int o = 4; o <= 16; o <<= 1) {
            p = fmaxf(p, __shfl_xor_sync(0xffffffffu, p, o));
            n = fminf(n, __shfl_xor_sync(0xffffffffu, n, o));
        }
        if (rq == 0) {
            const int cc = wc * 64 + (t >> 1) * 8 + cq + (t & 1);
            atomicMax(&scap[cc], __float_as_uint(p));
            atomicMin(&scan[cc], __float_as_uint(n));
        }
    }
    __syncthreads();
    atomicMax(&g_ap[col0 + tid], scap[tid]);
    atomicMin(&g_an[col0 + tid], scan[tid]);

    // ---------------- Last-CTA loss reduction ----------------
    __threadfence();
    __syncthreads();
    if (tid == 0) {
        unsigned old = atomicAdd(&g_cnt, 1u);
        *lastf = (old == NTILES - 1) ? 1 : 0;
    }
    __syncthreads();
    if (*lastf) {
        float s = 0.f;
        int c = 0;
        for (int i = tid; i < NROWS; i += 256) {
            float ap = __uint_as_float(g_ap[i]);
            float an = __uint_as_float(g_an[i]);
            if (ap > 0.f && isfinite(an)) {
                s += fmaxf(ap - an + MARGIN, 0.f);
                c += 1;
            }
        }
        #pragma unroll
        for (int o = 16; o; o >>= 1) {
            s += __shfl_xor_sync(0xffffffffu, s, o);
            c += __shfl_xor_sync(0xffffffffu, c, o);
        }
        float* ws = (float*)(smem + OFF_SQR);   // reuse meta space
        int*   wcnt = (int*)(smem + OFF_SQC);
        if ((tid & 31) == 0) { ws[tid >> 5] = s; wcnt[tid >> 5] = c; }
        __syncthreads();
        if (tid == 0) {
            float ts = 0.f; int tc = 0;
            #pragma unroll
            for (int w = 0; w < 8; w++) { ts += ws[w]; tc += wcnt[w]; }
            out[0] = tc > 0 ? ts / (float)tc : 0.f;
        }
    }
}

// ---------------------------------------------------------------------------
extern "C" void kernel_launch(void* const* d_in, const int* in_sizes, int n_in,
                              void* d_out, int out_size) {
    const float* features = (const float*)d_in[0];
    const int*   labels   = (const int*)d_in[1];
    float*       out      = (float*)d_out;
    (void)in_sizes; (void)n_in; (void)out_size;

    cudaFuncSetAttribute(gram_kernel, cudaFuncAttributeMaxDynamicSharedMemorySize,
                         SMEM_TOTAL);

    conv_kernel<<<NROWS, 256>>>(features);
    gram_kernel<<<NTILES, 256, SMEM_TOTAL>>>(labels, out);
}

// round 11
// speedup vs baseline: 3.1719x; 1.0874x over previous
#include <cuda_runtime.h>
#include <cuda_fp16.h>
#include <math_constants.h>
#include <cstdint>

// TripletLoss: features [4096,2048] f32, labels [4096] i32 -> scalar f32.
//  K0: convert x -> fp16 + row norms (fp32) + init accumulators/counter
//  K1: fp16 mma.sync Gram, 128x128 tiles (528 upper-tri CTAs), warp 32x64,
//      <=128 regs -> 2 CTAs/SM (4 warps/SMSP), 3-stage cp.async pipeline,
//      fused distance + batch-hard epilogue + last-CTA loss reduction.

#define NROWS 4096
#define DDIM  2048
#define MARGIN 0.3f

#define TM 128
#define TN 128
#define BK 64
#define NCHUNK (DDIM / BK)   // 32
#define NTILES 528           // 32*33/2

__device__ float        g_sq[NROWS];
__device__ unsigned int g_ap[NROWS];
__device__ unsigned int g_an[NROWS];
__device__ unsigned int g_cnt;
__device__ __half       g_F[(size_t)NROWS * DDIM];    // 16 MB

// ---------------- SMEM layout (dynamic, 2 CTAs/SM) ----------------
// Stage (32KB): A 128x64 fp16 (16K, 128B rows) | B 128x64 fp16 (16K)
#define STAGE_BYTES 32768u
#define OFF_A 0u
#define OFF_B 16384u
#define META   98304u                // after 3 stages
#define OFF_LR      (META + 0u)      // int[128]
#define OFF_LC      (META + 512u)    // int[128]
#define OFF_SQR     (META + 1024u)   // float[128]
#define OFF_SQC     (META + 1536u)   // float[128]
#define OFF_SCAP    (META + 2048u)   // uint[128]
#define OFF_SCAN    (META + 2560u)   // uint[128]
#define OFF_LAST    (META + 3072u)   // int flag
#define SMEM_TOTAL  (META + 3200u)   // ~101.5 KB -> 2 CTAs/SM

// ---------------- PTX helpers ----------------
__device__ __forceinline__ uint32_t smem_u32(const void* p) {
    uint32_t a;
    asm("{ .reg .u64 t; cvta.to.shared.u64 t, %1; cvt.u32.u64 %0, t; }" : "=r"(a) : "l"(p));
    return a;
}
__device__ __forceinline__ void cp16(uint32_t saddr, const void* gaddr) {
    asm volatile("cp.async.cg.shared.global [%0], [%1], 16;" :: "r"(saddr), "l"(gaddr));
}
__device__ __forceinline__ void cp_commit() {
    asm volatile("cp.async.commit_group;" ::: "memory");
}
template <int N> __device__ __forceinline__ void cp_wait() {
    asm volatile("cp.async.wait_group %0;" :: "n"(N) : "memory");
}
__device__ __forceinline__ void ldsm4(uint32_t (&r)[4], uint32_t a) {
    asm volatile("ldmatrix.sync.aligned.m8n8.x4.shared.b16 {%0,%1,%2,%3}, [%4];"
                 : "=r"(r[0]), "=r"(r[1]), "=r"(r[2]), "=r"(r[3]) : "r"(a));
}
__device__ __forceinline__ void mma_f16(float (&c)[4], const uint32_t (&a)[4],
                                        uint32_t b0, uint32_t b1) {
    asm volatile(
        "mma.sync.aligned.m16n8k16.row.col.f32.f16.f16.f32 "
        "{%0,%1,%2,%3}, {%4,%5,%6,%7}, {%8,%9}, {%0,%1,%2,%3};"
        : "+f"(c[0]), "+f"(c[1]), "+f"(c[2]), "+f"(c[3])
        : "r"(a[0]), "r"(a[1]), "r"(a[2]), "r"(a[3]), "r"(b0), "r"(b1));
}
// 128B-row swizzle
__device__ __forceinline__ uint32_t swz(uint32_t off) {
    return off ^ ((off >> 3) & 0x70);
}

// ---------------------------------------------------------------------------
// K0: fp16 convert + row squared norms + init.
// ---------------------------------------------------------------------------
__global__ __launch_bounds__(256) void conv_kernel(const float* __restrict__ x) {
    const int row = blockIdx.x;
    const float4* xr = (const float4*)(x + (size_t)row * DDIM);
    __half2* fp = (__half2*)(g_F + (size_t)row * DDIM);
    float s = 0.f;
    #pragma unroll 2
    for (int i = threadIdx.x; i < DDIM / 4; i += 256) {
        float4 v = xr[i];
        s += v.x * v.x + v.y * v.y + v.z * v.z + v.w * v.w;
        fp[2 * i + 0] = __floats2half2_rn(v.x, v.y);
        fp[2 * i + 1] = __floats2half2_rn(v.z, v.w);
    }
    #pragma unroll
    for (int o = 16; o; o >>= 1) s += __shfl_xor_sync(0xffffffffu, s, o);
    __shared__ float ws[8];
    if ((threadIdx.x & 31) == 0) ws[threadIdx.x >> 5] = s;
    __syncthreads();
    if (threadIdx.x == 0) {
        float t = 0.f;
        #pragma unroll
        for (int w = 0; w < 8; w++) t += ws[w];
        g_sq[row] = t;
        g_ap[row] = 0u;
        g_an[row] = 0x7f800000u;
        if (row == 0) g_cnt = 0u;
    }
}

// ---------------------------------------------------------------------------
// K1: fp16 Gram + fused batch-hard epilogue + last-CTA loss.
// 8 warps, CTA 128x128, warp 32x64 (4x2 grid). 3-stage pipeline, 2 CTAs/SM.
// ---------------------------------------------------------------------------
__global__ __launch_bounds__(256, 2) void gram_kernel(const int* __restrict__ lbl,
                                                      float* __restrict__ out) {
    extern __shared__ __align__(1024) char smem[];
    // linear bid -> (rt, ct), ct >= rt, row-major over the upper triangle
    int rt = 0, ct = 0;
    {
        int rem = blockIdx.x;
        #pragma unroll 1
        for (int r = 0; r < 32; ++r) {
            int cnt = 32 - r;
            if (rem < cnt) { rt = r; ct = r + rem; break; }
            rem -= cnt;
        }
    }
    const int row0 = rt * TM;
    const int col0 = ct * TN;
    const int tid = threadIdx.x;
    const int wid = tid >> 5;
    const int lid = tid & 31;
    const int wr = wid >> 1;       // warp row 0..3 (32 rows each)
    const int wc = wid & 1;        // warp col 0..1 (64 cols each)
    const uint32_t sb = smem_u32(smem);

    int*      lr   = (int*)(smem + OFF_LR);
    int*      lc   = (int*)(smem + OFF_LC);
    float*    sqr  = (float*)(smem + OFF_SQR);
    float*    sqc  = (float*)(smem + OFF_SQC);
    unsigned* scap = (unsigned*)(smem + OFF_SCAP);
    unsigned* scan = (unsigned*)(smem + OFF_SCAN);
    int*      lastf = (int*)(smem + OFF_LAST);

    if (tid < 128) {
        lr[tid]   = lbl[row0 + tid];
        sqr[tid]  = g_sq[row0 + tid];
        lc[tid]   = lbl[col0 + tid];
        sqc[tid]  = g_sq[col0 + tid];
        scap[tid] = 0u;
        scan[tid] = 0x7f800000u;
    }

    auto load_chunk = [&](int n) {
        const int k0 = n * BK;
        const uint32_t base = sb + (uint32_t)(n % 3) * STAGE_BYTES;
        #pragma unroll
        for (int u4 = 0; u4 < 4; ++u4) {               // A: 128 rows x 8 segs
            int u = tid + u4 * 256;
            int r = u >> 3, s = u & 7;
            cp16(base + OFF_A + swz((uint32_t)u << 4),
                 g_F + (size_t)(row0 + r) * DDIM + k0 + s * 8);
        }
        #pragma unroll
        for (int u4 = 0; u4 < 4; ++u4) {               // B: 128 rows x 8 segs
            int u = tid + u4 * 256;
            int r = u >> 3, s = u & 7;
            cp16(base + OFF_B + swz((uint32_t)u << 4),
                 g_F + (size_t)(col0 + r) * DDIM + k0 + s * 8);
        }
        cp_commit();
    };

    float acc[2][8][4];
    #pragma unroll
    for (int i = 0; i < 2; i++)
        #pragma unroll
        for (int j = 0; j < 8; j++)
            #pragma unroll
            for (int v = 0; v < 4; v++) acc[i][j][v] = 0.f;

    const int fr = lid & 15;
    const uint32_t kb16 = (uint32_t)(lid >> 4) * 16;

    load_chunk(0);
    load_chunk(1);

    #pragma unroll 1
    for (int c = 0; c < NCHUNK; ++c) {
        // chunk c landed; barrier also guards buffer (c+2)%3 (= chunk c-1's)
        if (c < NCHUNK - 1) cp_wait<1>();
        else                cp_wait<0>();
        __syncthreads();
        if (c + 2 < NCHUNK) load_chunk(c + 2);

        const uint32_t base = sb + (uint32_t)(c % 3) * STAGE_BYTES;
        const uint32_t arow = (uint32_t)(wr * 32 + fr);
        const uint32_t brow = (uint32_t)(wc * 64 + fr);

        #pragma unroll
        for (int ks = 0; ks < 4; ++ks) {               // K=16 per step
            const uint32_t kb = (uint32_t)ks * 32 + kb16;
            uint32_t ah[2][4], bh[4][4];
            #pragma unroll
            for (int i = 0; i < 2; ++i)
                ldsm4(ah[i], base + OFF_A + swz(((arow + i * 16) << 7) + kb));
            #pragma unroll
            for (int p = 0; p < 4; ++p)
                ldsm4(bh[p], base + OFF_B + swz(((brow + p * 16) << 7) + kb));
            #pragma unroll
            for (int i = 0; i < 2; ++i)
                #pragma unroll
                for (int j = 0; j < 8; ++j)
                    mma_f16(acc[i][j], ah[i],
                            (j & 1) ? bh[j >> 1][1] : bh[j >> 1][0],
                            (j & 1) ? bh[j >> 1][3] : bh[j >> 1][2]);
        }
    }

    // ---------------- Epilogue ----------------
    const int rq = lid >> 2;
    const int cq = (lid & 3) * 2;
    float rowP[4], rowN[4], colP[16], colN[16];
    #pragma unroll
    for (int t = 0; t < 4; t++)  { rowP[t] = 0.f; rowN[t] = CUDART_INF_F; }
    #pragma unroll
    for (int t = 0; t < 16; t++) { colP[t] = 0.f; colN[t] = CUDART_INF_F; }

    #pragma unroll
    for (int i = 0; i < 2; ++i) {
        const int rlo = wr * 32 + i * 16 + rq;
        const int rhi = rlo + 8;
        const float sq_lo = sqr[rlo], sq_hi = sqr[rhi];
        const int   ll_lo = lr[rlo],  ll_hi = lr[rhi];
        #pragma unroll
        for (int j = 0; j < 8; ++j) {
            const int cbase = wc * 64 + j * 8 + cq;
            #pragma unroll
            for (int v = 0; v < 4; ++v) {
                const int rloc = (v & 2) ? rhi : rlo;
                const int cloc = cbase + (v & 1);
                const float sqi = (v & 2) ? sq_hi : sq_lo;
                const int   li  = (v & 2) ? ll_hi : ll_lo;
                float d2 = fmaf(acc[i][j][v], -2.f, sqi + sqc[cloc]);
                float d  = d2 > 0.f ? sqrtf(d2) : 0.f;
                if (row0 + rloc == col0 + cloc) d = 0.f;   // exact diagonal
                const bool pos = (li == lc[cloc]);
                const float pv = pos ? d : 0.f;
                const float nv = pos ? CUDART_INF_F : d;
                const int ri = i * 2 + ((v & 2) >> 1);
                const int ci = j * 2 + (v & 1);
                rowP[ri] = fmaxf(rowP[ri], pv);
                rowN[ri] = fminf(rowN[ri], nv);
                colP[ci] = fmaxf(colP[ci], pv);
                colN[ci] = fminf(colN[ci], nv);
            }
        }
    }
    #pragma unroll
    for (int t = 0; t < 4; ++t) {
        float p = rowP[t], n = rowN[t];
        #pragma unroll
        for (int o = 1; o <= 2; o <<= 1) {
            p = fmaxf(p, __shfl_xor_sync(0xffffffffu, p, o));
            n = fminf(n, __shfl_xor_sync(0xffffffffu, n, o));
        }
        if ((lid & 3) == 0) {
            const int grow = row0 + wr * 32 + (t >> 1) * 16 + rq + (t & 1) * 8;
            atomicMax(&g_ap[grow], __float_as_uint(p));
            atomicMin(&g_an[grow], __float_as_uint(n));
        }
    }
    #pragma unroll
    for (int t = 0; t < 16; ++t) {
        float p = colP[t], n = colN[t];
        #pragma unroll
        for (int o = 4; o <= 16; o <<= 1) {
            p = fmaxf(p, __shfl_xor_sync(0xffffffffu, p, o));
            n = fminf(n, __shfl_xor_sync(0xffffffffu, n, o));
        }
        if (rq == 0) {
            const int cc = wc * 64 + (t >> 1) * 8 + cq + (t & 1);
            atomicMax(&scap[cc], __float_as_uint(p));
            atomicMin(&scan[cc], __float_as_uint(n));
        }
    }
    __syncthreads();
    if (tid < 128) {
        atomicMax(&g_ap[col0 + tid], scap[tid]);
        atomicMin(&g_an[col0 + tid], scan[tid]);
    }

    // ---------------- Last-CTA loss reduction ----------------
    __threadfence();
    __syncthreads();
    if (tid == 0) {
        unsigned old = atomicAdd(&g_cnt, 1u);
        *lastf = (old == NTILES - 1) ? 1 : 0;
    }
    __syncthreads();
    if (*lastf) {
        float s = 0.f;
        int c = 0;
        for (int i = tid; i < NROWS; i += 256) {
            float ap = __uint_as_float(g_ap[i]);
            float an = __uint_as_float(g_an[i]);
            if (ap > 0.f && isfinite(an)) {
                s += fmaxf(ap - an + MARGIN, 0.f);
                c += 1;
            }
        }
        #pragma unroll
        for (int o = 16; o; o >>= 1) {
            s += __shfl_xor_sync(0xffffffffu, s, o);
            c += __shfl_xor_sync(0xffffffffu, c, o);
        }
        float* ws = (float*)(smem + OFF_SQR);   // reuse meta space
        int*   wcnt = (int*)(smem + OFF_SQC);
        if ((tid & 31) == 0) { ws[tid >> 5] = s; wcnt[tid >> 5] = c; }
        __syncthreads();
        if (tid == 0) {
            float ts = 0.f; int tc = 0;
            #pragma unroll
            for (int w = 0; w < 8; w++) { ts += ws[w]; tc += wcnt[w]; }
            out[0] = tc > 0 ? ts / (float)tc : 0.f;
        }
    }
}

// ---------------------------------------------------------------------------
extern "C" void kernel_launch(void* const* d_in, const int* in_sizes, int n_in,
                              void* d_out, int out_size) {
    const float* features = (const float*)d_in[0];
    const int*   labels   = (const int*)d_in[1];
    float*       out      = (float*)d_out;
    (void)in_sizes; (void)n_in; (void)out_size;

    cudaFuncSetAttribute(gram_kernel, cudaFuncAttributeMaxDynamicSharedMemorySize,
                         SMEM_TOTAL);

    conv_kernel<<<NROWS, 256>>>(features);
    gram_kernel<<<NTILES, 256, SMEM_TOTAL>>>(labels, out);
}